// round 9
// baseline (speedup 1.0000x reference)
#include <cuda_runtime.h>
#include <math.h>

#define NB       4
#define NPER     100000
#define NSOLS    8
#define EBLOCKS  1184          // 8 CTAs * 148 SMs
#define SEGS     296           // EBLOCKS / NB : loadvol segments per batch
#define ROWS_SEG 338           // ceil(NPER / SEGS); 296*338 = 100048 >= 100000

// Per-block partial sums (fully overwritten every call — no zeroing kernel).
// Column-major per accumulator: k_reduce reads coalesced runs.
__device__ double g_epart[NB * NSOLS * EBLOCKS];   // [32][1184]
__device__ double g_lpart[NB * NSOLS * SEGS];      // [32][296]
__device__ double g_vpart[NB * SEGS];              // [4][296]

// Stage-2 results + completion ticket (self-resetting for graph replay).
__device__ double   g_red_e[NB * NSOLS];
__device__ double   g_red_l[NB * NSOLS];
__device__ double   g_red_v[NB];
__device__ unsigned g_cnt = 0;

// ---------------------------------------------------------------------------
// Fused kernel:
//  Prologue: loadvol over a flat float4 stream (dense, lane-consecutive
//  loads; s-half = f&1 = tid&1, fixed per thread).
//  Main loop: lane quad handles one nnz; lane ql loads float2 = s {2ql,2ql+1}
//     -> one LDG.64 covers 8 nnz / 8 distinct random 128B lines.
// ---------------------------------------------------------------------------
__global__ void k_main(const float* __restrict__ x,
                       const float* __restrict__ rhs,
                       const float* __restrict__ mass,
                       const int*   __restrict__ rows,
                       const int*   __restrict__ cols,
                       const float* __restrict__ vals,
                       int nnz) {
    __shared__ double s_l[NSOLS];
    __shared__ double s_v;
    __shared__ double s_e[NB * NSOLS];

    const int tid  = threadIdx.x;
    const int lane = tid & 31;
    const int blk  = blockIdx.x;
    const int b    = blk & (NB - 1);
    const int seg  = blk >> 2;             // 0..SEGS-1

    if (tid < NSOLS)      s_l[tid] = 0.0;
    if (tid == NSOLS)     s_v = 0.0;
    if (tid < NB * NSOLS) s_e[tid] = 0.0;
    __syncthreads();

    // ---------------- loadvol prologue (dense flat-float4) ----------------
    {
        const float4* x4 = (const float4*)x;
        const float4* r4 = (const float4*)rhs;

        int n0 = seg * ROWS_SEG;
        int n1 = n0 + ROWS_SEG; if (n1 > NPER) n1 = NPER;
        int f0 = (b * NPER + n0) * 2;      // first float4 index (even)
        int f1 = (b * NPER + n1) * 2;      // end

        const int h = tid & 1;             // s-half: f parity == tid parity

        float acc4[4] = {0.0f, 0.0f, 0.0f, 0.0f};
        float accV = 0.0f;

        for (int f = f0 + tid; f < f1; f += 256) {
            float4 xv = x4[f];
            float4 rv = r4[f];
            float  m  = mass[f >> 1];      // lane pairs broadcast-coalesce
            acc4[0] += m * rv.x * xv.x;
            acc4[1] += m * rv.y * xv.y;
            acc4[2] += m * rv.z * xv.z;
            acc4[3] += m * rv.w * xv.w;
            if (h == 0) accV += m;         // count each row's mass once
        }

        // butterfly over xor 2,4,8,16 — preserves parity bit0
#pragma unroll
        for (int off = 2; off < 32; off <<= 1) {
#pragma unroll
            for (int j = 0; j < 4; j++)
                acc4[j] += __shfl_xor_sync(0xffffffffu, acc4[j], off);
            accV += __shfl_xor_sync(0xffffffffu, accV, off);
        }
        // lane0: s0-3 sums (even lanes), lane1: s4-7 sums (odd lanes)
        if (lane < 2) {
#pragma unroll
            for (int j = 0; j < 4; j++)
                atomicAdd(&s_l[lane * 4 + j], (double)acc4[j]);
            if (lane == 0) atomicAdd(&s_v, (double)accV);
        }
    }

    // ---------------- energy main loop ----------------
    {
        const int gtid  = blk * blockDim.x + tid;
        const int ql    = gtid & 3;                   // s-pair index 0..3
        const int quad  = gtid >> 2;                  // starting nnz index
        const int qstep = (gridDim.x * blockDim.x) >> 2;

        const float2* x2 = (const float2*)x;

        float acc[NB][2];
#pragma unroll
        for (int bb = 0; bb < NB; bb++) { acc[bb][0] = 0.0f; acc[bb][1] = 0.0f; }

        for (int i = quad; i < nnz; i += qstep) {
            unsigned r = (unsigned)__ldcs(&rows[i]);  // streaming, no reuse
            unsigned c = (unsigned)__ldcs(&cols[i]);
            float    v = __ldcs(&vals[i]);

            float2 xr = __ldg(&x2[r * 4u + (unsigned)ql]);
            float2 xc = __ldg(&x2[c * 4u + (unsigned)ql]);

            int bnz = (int)(r / (unsigned)NPER);

            float t0 = v * xr.x * xc.x;
            float t1 = v * xr.y * xc.y;

#pragma unroll
            for (int bb = 0; bb < NB; bb++) {
                if (bb == bnz) {
                    acc[bb][0] += t0;
                    acc[bb][1] += t1;
                }
            }
        }

        // butterfly over the 8 quads of the warp (xor 4,8,16 keeps ql fixed)
#pragma unroll
        for (int off = 4; off < 32; off <<= 1) {
#pragma unroll
            for (int bb = 0; bb < NB; bb++) {
                acc[bb][0] += __shfl_xor_sync(0xffffffffu, acc[bb][0], off);
                acc[bb][1] += __shfl_xor_sync(0xffffffffu, acc[bb][1], off);
            }
        }
        if (lane < 4) {
#pragma unroll
            for (int bb = 0; bb < NB; bb++) {
                atomicAdd(&s_e[bb * NSOLS + lane * 2 + 0], (double)acc[bb][0]);
                atomicAdd(&s_e[bb * NSOLS + lane * 2 + 1], (double)acc[bb][1]);
            }
        }
    }
    __syncthreads();

    // ---------------- write per-block partials (compact) ----------------
    if (tid < NB * NSOLS) {
        g_epart[tid * EBLOCKS + blk] = s_e[tid];
        if ((tid >> 3) == b)
            g_lpart[tid * SEGS + seg] = s_l[tid & 7];
    }
    if (tid == b)
        g_vpart[b * SEGS + seg] = s_v;
}

// ---------------------------------------------------------------------------
// Stage 2: 32 blocks, block w reduces accumulator column w in parallel.
// Last-finished block (atomic ticket) computes the scalar epilogue.
// Ticket self-resets so the kernel is graph-replay safe and deterministic.
// ---------------------------------------------------------------------------
__global__ void k_reduce(float* __restrict__ out) {
    __shared__ double se[8], slm[8], sv[8];
    __shared__ int is_last;

    const int w    = blockIdx.x;          // column 0..31
    const int tid  = threadIdx.x;
    const int wid  = tid >> 5;
    const int lane = tid & 31;

    double e = 0.0, l = 0.0, v = 0.0;
    for (int i = tid; i < EBLOCKS; i += 256) e += g_epart[w * EBLOCKS + i];
    for (int i = tid; i < SEGS; i += 256)    l += g_lpart[w * SEGS + i];
    if (w < NB)
        for (int i = tid; i < SEGS; i += 256) v += g_vpart[w * SEGS + i];

#pragma unroll
    for (int off = 16; off >= 1; off >>= 1) {
        e += __shfl_xor_sync(0xffffffffu, e, off);
        l += __shfl_xor_sync(0xffffffffu, l, off);
        v += __shfl_xor_sync(0xffffffffu, v, off);
    }
    if (lane == 0) { se[wid] = e; slm[wid] = l; sv[wid] = v; }
    __syncthreads();

    if (tid == 0) {
        double E = 0.0, L = 0.0, V = 0.0;
#pragma unroll
        for (int i = 0; i < 8; i++) { E += se[i]; L += slm[i]; V += sv[i]; }
        g_red_e[w] = E;
        g_red_l[w] = L;
        if (w < NB) g_red_v[w] = V;
        __threadfence();
        is_last = (atomicAdd(&g_cnt, 1u) == 31u);
    }
    __syncthreads();

    if (is_last && tid < 32) {
        __threadfence();
        // lane = b*8 + s
        double a   = g_red_e[tid];
        double L   = g_red_l[tid];
        double vol = g_red_v[tid >> 3];

        double sigma = L / fmax(a, 1e-4);
        double kkt_e = (0.5 * a * sigma - L) * sigma / vol;
        double cmp_b = sigma * L / vol;
        double contrib = (0.5 * kkt_e - 0.5 * cmp_b) * (1.0 / 32.0);

#pragma unroll
        for (int off = 16; off >= 1; off >>= 1)
            contrib += __shfl_xor_sync(0xffffffffu, contrib, off);

        if (tid == 0) {
            out[0] = (float)contrib;
            g_cnt = 0;                     // reset ticket for next replay
        }
    }
}

// ---------------------------------------------------------------------------
// Launch
// inputs (metadata order): x_hat, rhs, A_ind(int32), A_val, subspace(unused), mass
// ---------------------------------------------------------------------------
extern "C" void kernel_launch(void* const* d_in, const int* in_sizes, int n_in,
                              void* d_out, int out_size) {
    const float* x_hat = (const float*)d_in[0];
    const float* rhs   = (const float*)d_in[1];
    const int*   A_ind = (const int*)d_in[2];
    const float* A_val = (const float*)d_in[3];
    const float* mass  = (const float*)d_in[5];

    int nnz = in_sizes[3];
    const int* rows = A_ind;          // A_ind[0, :]
    const int* cols = A_ind + nnz;    // A_ind[1, :]

    k_main<<<EBLOCKS, 256>>>(x_hat, rhs, mass, rows, cols, A_val, nnz);
    k_reduce<<<32, 256>>>((float*)d_out);
}